// round 6
// baseline (speedup 1.0000x reference)
#include <cuda_runtime.h>
#include <cstdint>
#include <math.h>

// Binary MLP B=16384, D=H=1024, C=10 using legacy int8 mma.sync (portable PTX).
// +-1 tensors stored as int8 (0x01 / 0xFF). Hidden layers: exact s8 GEMM with
// s32 accum; BatchNorm+sign folded to one integer threshold per neuron applied
// in the epilogue; output written as int8 +-1 for the next layer.

#define NBATCH 16384
#define HDIM   1024

// -------- device scratch (allocation-free rule) --------
__device__ uint8_t  g_a8[NBATCH * HDIM];      // activations ping
__device__ uint8_t  g_b8[NBATCH * HDIM];      // activations pong
__device__ uint8_t  g_w8[3 * HDIM * HDIM];    // int8 weights [layer][n][k]
__device__ int2     g_thri[3 * HDIM];         // (mul, thr): bit = (s*mul >= thr)
__device__ unsigned g_w4p[320];               // packed W4 sign bits (1 => negative)

__device__ __forceinline__ uint32_t smem_u32(const void* p) {
    uint32_t a;
    asm("{ .reg .u64 t; cvta.to.shared.u64 t, %1; cvt.u32.u64 %0, t; }" : "=r"(a) : "l"(p));
    return a;
}

// ======================= prep kernels =======================
__global__ void conv_x(const float* __restrict__ x, uint8_t* __restrict__ out) {
    int t = blockIdx.x * blockDim.x + threadIdx.x;
    if (t >= NBATCH * HDIM / 4) return;
    float4 v = reinterpret_cast<const float4*>(x)[t];
    uchar4 o;
    o.x = (v.x >= 0.5f) ? 0x01 : 0xFF;   // sign(2x-1)
    o.y = (v.y >= 0.5f) ? 0x01 : 0xFF;
    o.z = (v.z >= 0.5f) ? 0x01 : 0xFF;
    o.w = (v.w >= 0.5f) ? 0x01 : 0xFF;
    reinterpret_cast<uchar4*>(out)[t] = o;
}

__global__ void conv_w(const float* __restrict__ W, uint8_t* __restrict__ out) {
    int t = blockIdx.x * blockDim.x + threadIdx.x;
    if (t >= HDIM * HDIM / 4) return;
    float4 v = reinterpret_cast<const float4*>(W)[t];
    uchar4 o;
    o.x = (v.x >= 0.0f) ? 0x01 : 0xFF;
    o.y = (v.y >= 0.0f) ? 0x01 : 0xFF;
    o.z = (v.z >= 0.0f) ? 0x01 : 0xFF;
    o.w = (v.w >= 0.0f) ? 0x01 : 0xFF;
    reinterpret_cast<uchar4*>(out)[t] = o;
}

// bit = (s*mul >= thr) with s = exact integer pre-BN dot (range [-1024,1024], even)
__global__ void thr_kernel(const float* __restrict__ g, const float* __restrict__ b,
                           const float* __restrict__ m, const float* __restrict__ v,
                           int2* __restrict__ out) {
    int n = blockIdx.x * blockDim.x + threadIdx.x;
    if (n >= HDIM) return;
    double sc = (double)g[n] / sqrt((double)v[n] + 1e-5);
    int mul, t;
    if (sc > 0.0) {
        double T = (1024.0 - (double)m[n] + (double)b[n] / sc) * 0.5;
        T = fmin(fmax(T, -2000.0), 2000.0);
        mul = 1;  t = (int)(1024.0 - 2.0 * floor(T));      // bit <=> s >= A
    } else if (sc < 0.0) {
        double T = (1024.0 - (double)m[n] + (double)b[n] / sc) * 0.5;
        T = fmin(fmax(T, -2000.0), 2000.0);
        mul = -1; t = -(int)(1024.0 - 2.0 * ceil(T));      // bit <=> s <= B
    } else {
        mul = 0;  t = ((double)b[n] >= 0.0) ? 0 : 1;
    }
    out[n] = make_int2(mul, t);
}

__global__ void pack_w4(const float* __restrict__ W4) {
    int t = threadIdx.x;
    if (t >= 320) return;
    int c = t >> 5, j = t & 31;
    const float* p = W4 + (size_t)c * 1024 + j * 32;
    unsigned bits = 0;
#pragma unroll
    for (int l = 0; l < 32; l++) bits |= (p[l] < 0.0f ? 1u : 0u) << l;
    g_w4p[t] = bits;
}

// ======================= s8 GEMM layer (mma.sync) =======================
// grid (128, 8): 128x128 output tile per CTA, K=1024 in 8 chunks of 128.
// 8 warps in 4x2: warp tile 32 rows x 64 cols; m16n8k32 fragments loaded with
// plain LDS from SW128-xor swizzled smem (conflict-free).
__global__ void __launch_bounds__(256)
gemm_layer(const uint8_t* __restrict__ Ain, const uint8_t* __restrict__ Wt,
           uint8_t* __restrict__ Aout, const int2* __restrict__ thr) {
    extern __shared__ uint8_t ds[];             // 2 x (A 16KB + B 16KB)
    const int tid  = threadIdx.x;
    const int lane = tid & 31, wid = tid >> 5;
    const int gidr = lane >> 2, tig = lane & 3;
    const int m0 = blockIdx.x * 128, n0 = blockIdx.y * 128;
    const int wm = (wid & 3) * 32, wn = (wid >> 2) * 64;

    int acc[2][8][4];
#pragma unroll
    for (int a = 0; a < 2; a++)
#pragma unroll
        for (int b = 0; b < 8; b++)
#pragma unroll
            for (int c = 0; c < 4; c++) acc[a][b][c] = 0;

    // stage chunk kc into buffer kc&1 (A and B tiles, swizzled)
    auto stage = [&](int kc) {
        uint8_t* As = ds + (kc & 1) * 32768;
        uint8_t* Bs = As + 16384;
        const uint8_t* ga = Ain + (size_t)m0 * 1024 + kc * 128;
        const uint8_t* gb = Wt  + (size_t)n0 * 1024 + kc * 128;
#pragma unroll
        for (int l = 0; l < 4; l++) {
            int i = l * 256 + tid;
            int r = i >> 3, c16 = i & 7;
            uint32_t sw = (uint32_t)(c16 * 16) ^ (uint32_t)((r & 7) * 16);
            uint32_t da = smem_u32(As + r * 128 + sw);
            uint32_t db = smem_u32(Bs + r * 128 + sw);
            asm volatile("cp.async.cg.shared.global [%0], [%1], 16;"
                         :: "r"(da), "l"(ga + (size_t)r * 1024 + c16 * 16) : "memory");
            asm volatile("cp.async.cg.shared.global [%0], [%1], 16;"
                         :: "r"(db), "l"(gb + (size_t)r * 1024 + c16 * 16) : "memory");
        }
        asm volatile("cp.async.commit_group;" ::: "memory");
    };

    stage(0);
    for (int kc = 0; kc < 8; kc++) {
        if (kc < 7) {
            stage(kc + 1);
            asm volatile("cp.async.wait_group 1;" ::: "memory");
        } else {
            asm volatile("cp.async.wait_group 0;" ::: "memory");
        }
        __syncthreads();

        const uint8_t* As = ds + (kc & 1) * 32768;
        const uint8_t* Bs = As + 16384;
#pragma unroll
        for (int kt = 0; kt < 4; kt++) {
            const int c0 = kt * 32 + tig * 4;
            int afr[2][4];
#pragma unroll
            for (int mt = 0; mt < 2; mt++) {
                int r0 = wm + mt * 16 + gidr, r1 = r0 + 8;
                afr[mt][0] = *(const int*)(As + r0 * 128 + ( c0       ^ ((r0 & 7) * 16)));
                afr[mt][1] = *(const int*)(As + r1 * 128 + ( c0       ^ ((r1 & 7) * 16)));
                afr[mt][2] = *(const int*)(As + r0 * 128 + ((c0 + 16) ^ ((r0 & 7) * 16)));
                afr[mt][3] = *(const int*)(As + r1 * 128 + ((c0 + 16) ^ ((r1 & 7) * 16)));
            }
#pragma unroll
            for (int nt = 0; nt < 8; nt++) {
                int n = wn + nt * 8 + gidr;
                int b0 = *(const int*)(Bs + n * 128 + ( c0       ^ ((n & 7) * 16)));
                int b1 = *(const int*)(Bs + n * 128 + ((c0 + 16) ^ ((n & 7) * 16)));
#pragma unroll
                for (int mt = 0; mt < 2; mt++) {
                    asm volatile(
                        "mma.sync.aligned.m16n8k32.row.col.s32.s8.s8.s32 "
                        "{%0,%1,%2,%3}, {%4,%5,%6,%7}, {%8,%9}, {%0,%1,%2,%3};"
                        : "+r"(acc[mt][nt][0]), "+r"(acc[mt][nt][1]),
                          "+r"(acc[mt][nt][2]), "+r"(acc[mt][nt][3])
                        : "r"(afr[mt][0]), "r"(afr[mt][1]), "r"(afr[mt][2]), "r"(afr[mt][3]),
                          "r"(b0), "r"(b1));
                }
            }
        }
        __syncthreads();
    }

    // epilogue: threshold -> int8 +-1, stage in smem (plain), coalesced store
    uint8_t* Os = ds;                            // buffer 0 free now
#pragma unroll
    for (int mt = 0; mt < 2; mt++) {
        int r0 = wm + mt * 16 + gidr;
#pragma unroll
        for (int nt = 0; nt < 8; nt++) {
            int coll = wn + nt * 8 + tig * 2;
            int2 t0 = thr[n0 + coll];
            int2 t1 = thr[n0 + coll + 1];
            unsigned y00 = (acc[mt][nt][0] * t0.x >= t0.y) ? 0x01u : 0xFFu;
            unsigned y01 = (acc[mt][nt][1] * t1.x >= t1.y) ? 0x01u : 0xFFu;
            unsigned y10 = (acc[mt][nt][2] * t0.x >= t0.y) ? 0x01u : 0xFFu;
            unsigned y11 = (acc[mt][nt][3] * t1.x >= t1.y) ? 0x01u : 0xFFu;
            *(uint16_t*)(Os + r0 * 128 + coll)       = (uint16_t)(y00 | (y01 << 8));
            *(uint16_t*)(Os + (r0 + 8) * 128 + coll) = (uint16_t)(y10 | (y11 << 8));
        }
    }
    __syncthreads();
#pragma unroll
    for (int l = 0; l < 4; l++) {
        int i = l * 256 + tid;
        int r = i >> 3, c16 = i & 7;
        *(uint4*)(Aout + (size_t)(m0 + r) * 1024 + n0 + c16 * 16) =
            *(const uint4*)(Os + r * 128 + c16 * 16);
    }
}

// ======================= final layer (C=10) + TensorNorm =======================
__global__ void final_kernel(const float* __restrict__ tnw, const float* __restrict__ tnb,
                             const float* __restrict__ tnm, const float* __restrict__ tnv,
                             float* __restrict__ out) {
    __shared__ unsigned sw4[320];
    const int tid = threadIdx.x;
    for (int i = tid; i < 320; i += blockDim.x) sw4[i] = g_w4p[i];
    __syncthreads();

    const int row  = (blockIdx.x * blockDim.x + tid) >> 5;
    const int lane = tid & 31;

    // sign-bit mask of 32 int8 bytes (bit=1 <=> -1)
    const uint32_t* ap = reinterpret_cast<const uint32_t*>(g_b8 + (size_t)row * 1024 + lane * 32);
    uint32_t mask = 0;
#pragma unroll
    for (int i = 0; i < 8; i++) {
        uint32_t u = ap[i];
        uint32_t nib = ((u >> 7) & 1) | ((u >> 14) & 2) | ((u >> 21) & 4) | ((u >> 28) & 8);
        mask |= nib << (4 * i);
    }

    float rs = (float)(1.0 / sqrt((double)tnv[0] + 1e-4));
    float wq = tnw[0], bq = tnb[0], mq = tnm[0];

    float sval = 0.f;
#pragma unroll
    for (int c = 0; c < 10; c++) {
        int d = __popc(mask ^ sw4[c * 32 + lane]);
        int P = __reduce_add_sync(0xffffffffu, d);
        if (lane == c) sval = (float)(1024 - 2 * P);
    }
    if (lane < 10) out[(size_t)row * 10 + lane] = ((sval - mq) * rs) * wq + bq;
}

// ======================= launch =======================
extern "C" void kernel_launch(void* const* d_in, const int* in_sizes, int n_in,
                              void* d_out, int out_size) {
    const float* x  = (const float*)d_in[0];
    const float* W1 = (const float*)d_in[1];
    const float* W2 = (const float*)d_in[2];
    const float* W3 = (const float*)d_in[3];
    const float* W4 = (const float*)d_in[4];
    const float* g1 = (const float*)d_in[5],  *b1 = (const float*)d_in[6];
    const float* m1 = (const float*)d_in[7],  *v1 = (const float*)d_in[8];
    const float* g2 = (const float*)d_in[9],  *b2 = (const float*)d_in[10];
    const float* m2 = (const float*)d_in[11], *v2 = (const float*)d_in[12];
    const float* g3 = (const float*)d_in[13], *b3 = (const float*)d_in[14];
    const float* m3 = (const float*)d_in[15], *v3 = (const float*)d_in[16];
    const float* tnw = (const float*)d_in[17], *tnb = (const float*)d_in[18];
    const float* tnm = (const float*)d_in[19], *tnv = (const float*)d_in[20];
    float* out = (float*)d_out;

    cudaFuncSetAttribute(gemm_layer, cudaFuncAttributeMaxDynamicSharedMemorySize, 65536);

    void *pa, *pb, *pw, *pt;
    cudaGetSymbolAddress(&pa, g_a8);
    cudaGetSymbolAddress(&pb, g_b8);
    cudaGetSymbolAddress(&pw, g_w8);
    cudaGetSymbolAddress(&pt, g_thri);
    uint8_t* a8 = (uint8_t*)pa;
    uint8_t* b8 = (uint8_t*)pb;
    uint8_t* w8 = (uint8_t*)pw;
    int2*    tv = (int2*)pt;

    conv_x<<<NBATCH * HDIM / 4 / 256, 256>>>(x, a8);
    conv_w<<<HDIM * HDIM / 4 / 256, 256>>>(W1, w8);
    conv_w<<<HDIM * HDIM / 4 / 256, 256>>>(W2, w8 + 1048576);
    conv_w<<<HDIM * HDIM / 4 / 256, 256>>>(W3, w8 + 2097152);
    thr_kernel<<<4, 256>>>(g1, b1, m1, v1, tv);
    thr_kernel<<<4, 256>>>(g2, b2, m2, v2, tv + 1024);
    thr_kernel<<<4, 256>>>(g3, b3, m3, v3, tv + 2048);
    pack_w4<<<1, 320>>>(W4);

    dim3 grid(128, 8);
    gemm_layer<<<grid, 256, 65536>>>(a8, w8,           b8, tv);
    gemm_layer<<<grid, 256, 65536>>>(b8, w8 + 1048576, a8, tv + 1024);
    gemm_layer<<<grid, 256, 65536>>>(a8, w8 + 2097152, b8, tv + 2048);

    final_kernel<<<NBATCH * 32 / 256, 256>>>(tnw, tnb, tnm, tnv, out);
}

// round 7
// speedup vs baseline: 2.3161x; 2.3161x over previous
#include <cuda_runtime.h>
#include <cstdint>
#include <math.h>

// Binary MLP B=16384, D=H=1024, C=10.
// Bit-packed XOR+POPC GEMMs with BatchNorm+sign folded into one integer
// threshold per neuron. Hot loop uses a hybrid bit-count: 10 words via naive
// POPC (quarter-rate POPC pipe) + 22 words via a carry-save-adder tree
// (full-rate ALU LOP3 pipe), balancing both pipes for ~1.8x over pure POPC.

#define NB       16384          // batch rows
#define KW       32             // 1024 bits / 32 words per row
#define HN       1024           // hidden neurons
#define ROWS_PB  128            // rows per block (layer kernel)
#define GRP_PB   8              // neuron groups (of 32) per block
#define THREADS  256

// Scratch (device globals: allocation-free rule)
__device__ unsigned g_act[2][NB * KW];     // ping-pong packed activations
__device__ unsigned g_wt[3][KW * HN];      // packed hidden weights, [word j][neuron n]
__device__ unsigned g_w4[10 * KW];         // packed output weights [c][j]

// forced single-LOP3 helpers
__device__ __forceinline__ unsigned lop3_96(unsigned a, unsigned b, unsigned c) { // a^b^c
    unsigned r;
    asm("lop3.b32 %0, %1, %2, %3, 0x96;" : "=r"(r) : "r"(a), "r"(b), "r"(c));
    return r;
}
__device__ __forceinline__ unsigned lop3_e8(unsigned a, unsigned b, unsigned c) { // maj(a,b,c)
    unsigned r;
    asm("lop3.b32 %0, %1, %2, %3, 0xE8;" : "=r"(r) : "r"(a), "r"(b), "r"(c));
    return r;
}
#define FA(a, b, c, s, cy) { s = lop3_96(a, b, c); cy = lop3_e8(a, b, c); }

// ---------------- input packing: bit = (2x-1 >= 0) ----------------
__global__ void pack_x_kernel(const float* __restrict__ x) {
    int t = blockIdx.x * blockDim.x + threadIdx.x;
    if (t >= NB * KW) return;
    int row = t >> 5;
    int w   = t & 31;
    const float4* p = reinterpret_cast<const float4*>(x + (size_t)row * 1024 + w * 32);
    unsigned bits = 0;
#pragma unroll
    for (int i = 0; i < 8; i++) {
        float4 v = p[i];
        bits |= ((2.0f * v.x - 1.0f) >= 0.0f ? 1u : 0u) << (4 * i + 0);
        bits |= ((2.0f * v.y - 1.0f) >= 0.0f ? 1u : 0u) << (4 * i + 1);
        bits |= ((2.0f * v.z - 1.0f) >= 0.0f ? 1u : 0u) << (4 * i + 2);
        bits |= ((2.0f * v.w - 1.0f) >= 0.0f ? 1u : 0u) << (4 * i + 3);
    }
    g_act[0][t] = bits;
}

// ---------------- weight packing (transposed) ----------------
__global__ void pack_w_kernel(const float* __restrict__ W, int widx) {
    int t = blockIdx.x * blockDim.x + threadIdx.x;
    if (t >= KW * HN) return;
    int n = t & (HN - 1);
    int j = t >> 10;
    const float4* p = reinterpret_cast<const float4*>(W + (size_t)n * 1024 + j * 32);
    unsigned bits = 0;
#pragma unroll
    for (int i = 0; i < 8; i++) {
        float4 v = p[i];
        bits |= (v.x >= 0.0f ? 1u : 0u) << (4 * i + 0);
        bits |= (v.y >= 0.0f ? 1u : 0u) << (4 * i + 1);
        bits |= (v.z >= 0.0f ? 1u : 0u) << (4 * i + 2);
        bits |= (v.w >= 0.0f ? 1u : 0u) << (4 * i + 3);
    }
    g_wt[widx][j * HN + n] = bits;
}

__global__ void pack_w4_kernel(const float* __restrict__ W4) {
    int t = threadIdx.x;
    if (t >= 10 * KW) return;
    int c = t >> 5;
    int j = t & 31;
    const float4* p = reinterpret_cast<const float4*>(W4 + (size_t)c * 1024 + j * 32);
    unsigned bits = 0;
#pragma unroll
    for (int i = 0; i < 8; i++) {
        float4 v = p[i];
        bits |= (v.x >= 0.0f ? 1u : 0u) << (4 * i + 0);
        bits |= (v.y >= 0.0f ? 1u : 0u) << (4 * i + 1);
        bits |= (v.z >= 0.0f ? 1u : 0u) << (4 * i + 2);
        bits |= (v.w >= 0.0f ? 1u : 0u) << (4 * i + 3);
    }
    g_w4[c * KW + j] = bits;
}

// ---------------- hidden layer: binary GEMM + BN threshold + repack ----------------
// grid: (NB/ROWS_PB, HN/(GRP_PB*32)), block: 256 (8 warps, 1 neuron-group each)
__global__ void __launch_bounds__(THREADS)
layer_kernel(int src, int dst, int widx,
             const float* __restrict__ gg, const float* __restrict__ bb,
             const float* __restrict__ mm, const float* __restrict__ vv) {
    __shared__ uint4 sh_a[ROWS_PB][8];

    const int tid  = threadIdx.x;
    const int lane = tid & 31;
    const int wid  = tid >> 5;
    const int row0 = blockIdx.x * ROWS_PB;
    const int grp  = blockIdx.y * GRP_PB + wid;
    const int n    = grp * 32 + lane;

    // stage A tile: ROWS_PB rows x 32 words
    {
        const uint4* asrc = reinterpret_cast<const uint4*>(&g_act[src][(size_t)row0 * KW]);
        uint4* adst = &sh_a[0][0];
        for (int i = tid; i < ROWS_PB * 8; i += THREADS) adst[i] = asrc[i];
    }

    // per-lane weight cache (32 regs)
    unsigned w[KW];
    const unsigned* wt = &g_wt[widx][0];
#pragma unroll
    for (int j = 0; j < KW; j++) w[j] = wt[j * HN + n];

    // exact integer threshold from BN params (same as R1; rel_err 0.0 verified)
    int thr; unsigned neg;
    {
        double gd = (double)gg[n], vd = (double)vv[n];
        double md = (double)mm[n], bd = (double)bb[n];
        double sc = gd / sqrt(vd + 1e-5);
        if (sc > 0.0) {
            double T = (1024.0 - md + bd / sc) * 0.5;
            T = fmin(fmax(T, -2.0e9), 2.0e9);
            thr = (int)floor(T); neg = 0u;
        } else if (sc < 0.0) {
            double T = (1024.0 - md + bd / sc) * 0.5;
            T = fmin(fmax(T, -2.0e9), 2.0e9);
            thr = (int)ceil(T) - 1; neg = 1u;
        } else {
            thr = (bd >= 0.0) ? 0x7fffffff : (-0x7fffffff - 1); neg = 0u;
        }
    }
    __syncthreads();

    unsigned* out = &g_act[dst][0];
#pragma unroll 2
    for (int r = 0; r < ROWS_PB; ++r) {
        // load 32 words (broadcast LDS.128) and XOR with weights
        unsigned x[32];
#pragma unroll
        for (int i = 0; i < 8; i++) {
            uint4 av = sh_a[r][i];
            x[4 * i + 0] = av.x ^ w[4 * i + 0];
            x[4 * i + 1] = av.y ^ w[4 * i + 1];
            x[4 * i + 2] = av.z ^ w[4 * i + 2];
            x[4 * i + 3] = av.w ^ w[4 * i + 3];
        }

        // naive POPC on x[0..9]  (POPC pipe)
        int pn0 = __popc(x[0]) + __popc(x[1]);
        int pn1 = __popc(x[2]) + __popc(x[3]);
        int pn2 = __popc(x[4]) + __popc(x[5]);
        int pn3 = __popc(x[6]) + __popc(x[7]);
        int pn4 = __popc(x[8]) + __popc(x[9]);
        int pn  = ((pn0 + pn1) + (pn2 + pn3)) + pn4;

        // CSA tree on x[10..31] (22 words, 15 full adders on ALU pipe)
        unsigned s10,c10,s11,c11,s12,c12,s13,c13,s14,c14,s15,c15,s16,c16;
        FA(x[10], x[11], x[12], s10, c10);
        FA(x[13], x[14], x[15], s11, c11);
        FA(x[16], x[17], x[18], s12, c12);
        FA(x[19], x[20], x[21], s13, c13);
        FA(x[22], x[23], x[24], s14, c14);
        FA(x[25], x[26], x[27], s15, c15);
        FA(x[28], x[29], x[30], s16, c16);
        // weight-1 pool: s10..s16, x[31]
        unsigned s17,c17,s18,c18,s19,c19;
        FA(s10, s11, s12, s17, c17);
        FA(s13, s14, s15, s18, c18);
        FA(s17, s18, s16, s19, c19);
        int p1 = __popc(s19) + __popc(x[31]);
        // weight-2 pool: c10..c16, c17, c18, c19
        unsigned t0,d0,t1,d1,t2,d2,t3,d3;
        FA(c10, c11, c12, t0, d0);
        FA(c13, c14, c15, t1, d1);
        FA(c16, c17, c18, t2, d2);
        FA(t0,  t1,  t2,  t3, d3);
        int p2 = __popc(t3) + __popc(c19);
        // weight-4 pool: d0,d1,d2,d3
        unsigned t4,d4;
        FA(d0, d1, d2, t4, d4);
        int p4 = __popc(t4) + __popc(d3);
        // weight-8: d4
        int p8 = __popc(d4);

        int P = pn + p1 + 2 * p2 + 4 * p4 + 8 * p8;

        unsigned bit = ((P <= thr) ? 1u : 0u) ^ neg;
        unsigned wordbits = __ballot_sync(0xffffffffu, bit != 0u);
        if (lane == 0) out[(size_t)(row0 + r) * KW + grp] = wordbits;
    }
}

// ---------------- final layer (C=10) + TensorNorm ----------------
__global__ void final_kernel(const float* __restrict__ tnw, const float* __restrict__ tnb,
                             const float* __restrict__ tnm, const float* __restrict__ tnv,
                             float* __restrict__ out) {
    __shared__ unsigned sw[10 * KW];
    const int tid = threadIdx.x;
    for (int i = tid; i < 10 * KW; i += blockDim.x) sw[i] = g_w4[i];
    __syncthreads();

    int row = blockIdx.x * blockDim.x + tid;
    if (row >= NB) return;

    uint4 a[8];
    const uint4* p = reinterpret_cast<const uint4*>(&g_act[1][(size_t)row * KW]);
#pragma unroll
    for (int i = 0; i < 8; i++) a[i] = p[i];

    float rs = (float)(1.0 / sqrt((double)tnv[0] + 1e-4));
    float wq = tnw[0], bq = tnb[0], mq = tnm[0];

#pragma unroll
    for (int c = 0; c < 10; c++) {
        int P = 0;
#pragma unroll
        for (int i = 0; i < 8; i++) {
            P += __popc(a[i].x ^ sw[c * KW + 4 * i + 0]);
            P += __popc(a[i].y ^ sw[c * KW + 4 * i + 1]);
            P += __popc(a[i].z ^ sw[c * KW + 4 * i + 2]);
            P += __popc(a[i].w ^ sw[c * KW + 4 * i + 3]);
        }
        float s = (float)(1024 - 2 * P);
        out[(size_t)row * 10 + c] = ((s - mq) * rs) * wq + bq;
    }
}

extern "C" void kernel_launch(void* const* d_in, const int* in_sizes, int n_in,
                              void* d_out, int out_size) {
    const float* x  = (const float*)d_in[0];
    const float* W1 = (const float*)d_in[1];
    const float* W2 = (const float*)d_in[2];
    const float* W3 = (const float*)d_in[3];
    const float* W4 = (const float*)d_in[4];
    const float* g1 = (const float*)d_in[5],  *b1 = (const float*)d_in[6];
    const float* m1 = (const float*)d_in[7],  *v1 = (const float*)d_in[8];
    const float* g2 = (const float*)d_in[9],  *b2 = (const float*)d_in[10];
    const float* m2 = (const float*)d_in[11], *v2 = (const float*)d_in[12];
    const float* g3 = (const float*)d_in[13], *b3 = (const float*)d_in[14];
    const float* m3 = (const float*)d_in[15], *v3 = (const float*)d_in[16];
    const float* tnw = (const float*)d_in[17], *tnb = (const float*)d_in[18];
    const float* tnm = (const float*)d_in[19], *tnv = (const float*)d_in[20];
    float* out = (float*)d_out;

    pack_x_kernel<<<(NB * KW + 255) / 256, 256>>>(x);
    pack_w_kernel<<<(KW * HN + 255) / 256, 256>>>(W1, 0);
    pack_w_kernel<<<(KW * HN + 255) / 256, 256>>>(W2, 1);
    pack_w_kernel<<<(KW * HN + 255) / 256, 256>>>(W3, 2);
    pack_w4_kernel<<<1, 320>>>(W4);

    dim3 lgrid(NB / ROWS_PB, HN / (GRP_PB * 32));    // (128, 4)
    layer_kernel<<<lgrid, THREADS>>>(0, 1, 0, g1, b1, m1, v1);
    layer_kernel<<<lgrid, THREADS>>>(1, 0, 1, g2, b2, m2, v2);
    layer_kernel<<<lgrid, THREADS>>>(0, 1, 2, g3, b3, m3, v3);

    final_kernel<<<NB / 256, 256>>>(tnw, tnb, tnm, tnv, out);
}